// round 3
// baseline (speedup 1.0000x reference)
#include <cuda_runtime.h>

#define CDIM 128
#define OUTC 64
#define NMAX 50000
#define EMAX 600000
#define SEEDMAX 4096

// ---------------- scratch (no allocations allowed; 16B-aligned) ----------------
__device__ __align__(16) int   g_deg[NMAX];
__device__ __align__(16) int   g_off[NMAX + 1];
__device__ __align__(16) int   g_cursor[NMAX];
__device__ __align__(16) int   g_adj[EMAX];
__device__ __align__(16) float g_agg[(size_t)NMAX * CDIM];
__device__ __align__(16) float g_x1[(size_t)NMAX * CDIM];
__device__ __align__(16) float g_x2[(size_t)SEEDMAX * CDIM];
__device__ __align__(16) float g_WT[2 * 256 * CDIM];   // [layer][k 0..255][o 0..127]
__device__ __align__(16) float g_WhT[CDIM * OUTC];     // [k][o]

// ---------------- CSR build ----------------
__global__ void k_zero_deg(int n) {
    int i = blockIdx.x * blockDim.x + threadIdx.x;
    if (i < n) g_deg[i] = 0;
}

// edge_index is int32 on device (JAX x64 disabled downcasts jnp.int64 -> int32)
__global__ void k_hist(const int* __restrict__ dst, int E, int n) {
    int i = blockIdx.x * blockDim.x + threadIdx.x;
    if (i < E) {
        unsigned d = (unsigned)dst[i];
        if (d < (unsigned)n) atomicAdd(&g_deg[d], 1);
    }
}

// single-block exclusive scan over g_deg -> g_off, g_cursor
__global__ void k_scan(int n, int e_total) {
    __shared__ int warp_sums[32];
    __shared__ int s_carry;
    int lane = threadIdx.x & 31, wid = threadIdx.x >> 5;
    if (threadIdx.x == 0) s_carry = 0;
    __syncthreads();
    for (int base = 0; base < n; base += 1024) {
        int i = base + (int)threadIdx.x;
        int v = (i < n) ? g_deg[i] : 0;
        int s = v;
        #pragma unroll
        for (int o = 1; o < 32; o <<= 1) {
            int t = __shfl_up_sync(0xffffffffu, s, o);
            if (lane >= o) s += t;
        }
        if (lane == 31) warp_sums[wid] = s;
        __syncthreads();
        if (wid == 0) {
            int ws = warp_sums[lane];
            int w = ws;
            #pragma unroll
            for (int o = 1; o < 32; o <<= 1) {
                int t = __shfl_up_sync(0xffffffffu, w, o);
                if (lane >= o) w += t;
            }
            warp_sums[lane] = w - ws;   // exclusive prefix of warp sums
        }
        __syncthreads();
        int incl = s + warp_sums[wid] + s_carry;
        int excl = incl - v;
        if (i < n) { g_off[i] = excl; g_cursor[i] = excl; }
        __syncthreads();
        if (threadIdx.x == 1023) s_carry = incl;
        __syncthreads();
    }
    if (threadIdx.x == 0) g_off[n] = e_total;
}

__global__ void k_fill(const int* __restrict__ src,
                       const int* __restrict__ dst, int E, int n) {
    int i = blockIdx.x * blockDim.x + threadIdx.x;
    if (i < E) {
        unsigned d = (unsigned)dst[i];
        unsigned s = (unsigned)src[i];
        if (d < (unsigned)n && s < (unsigned)n) {
            int slot = atomicAdd(&g_cursor[d], 1);
            if (slot < EMAX) g_adj[slot] = (int)s;
        }
    }
}

// ---------------- weight pre-transpose ----------------
__global__ void k_prep(const float* __restrict__ Wn, const float* __restrict__ Wr,
                       const float* __restrict__ Wh) {
    int i = blockIdx.x * blockDim.x + threadIdx.x;
    if (i < 2 * 256 * CDIM) {
        int l = i / (256 * CDIM);
        int rem = i % (256 * CDIM);
        int k = rem / CDIM;
        int o = rem % CDIM;
        float v = (k < CDIM) ? Wn[l * CDIM * CDIM + o * CDIM + k]
                             : Wr[l * CDIM * CDIM + o * CDIM + (k - CDIM)];
        g_WT[i] = v;
    }
    if (i < CDIM * OUTC) {
        int k = i / OUTC, o = i % OUTC;
        g_WhT[i] = Wh[o * CDIM + k];
    }
}

// ---------------- mean aggregation: one warp per node, writes g_agg ----------------
__global__ void k_aggregate(const float* __restrict__ xext, int layer, int M) {
    const float* x = (layer == 0) ? xext : (const float*)g_x1;
    int warp = (int)((blockIdx.x * blockDim.x + threadIdx.x) >> 5);
    int lane = threadIdx.x & 31;
    if (warp >= M) return;
    int s0 = g_off[warp], s1 = g_off[warp + 1];
    float4 acc = make_float4(0.f, 0.f, 0.f, 0.f);
    for (int e = s0; e < s1; e++) {
        int sv = g_adj[e];
        float4 v = __ldg((const float4*)(x + (size_t)sv * CDIM) + lane);
        acc.x += v.x; acc.y += v.y; acc.z += v.z; acc.w += v.w;
    }
    float inv = 1.f / fmaxf((float)(s1 - s0), 1.f);
    float4 out = make_float4(acc.x * inv, acc.y * inv, acc.z * inv, acc.w * inv);
    ((float4*)(g_agg + (size_t)warp * CDIM))[lane] = out;
}

// ---------------- fused GEMM(K=256) + bias + LayerNorm + ReLU ----------------
// h[n][o] = sum_k agg[n][k]*Wn[o][k] + sum_k x[n][k]*Wr[o][k] + b[o]
// 64 rows x 128 cols per block, 256 threads; warp ty owns 8 full rows (LN via
// shuffles); K=256 streamed in 8 chunks of 32 through 24KB static shared.
__global__ void __launch_bounds__(256)
k_gemm_ln_relu(const float* __restrict__ xext, int layer, int M,
               const float* __restrict__ bias, const float* __restrict__ gamma,
               const float* __restrict__ beta)
{
    __shared__ __align__(16) float sW[32 * CDIM];   // [kk][o]  16KB
    __shared__ __align__(16) float sA[64 * 32];     // [row][kk] 8KB

    const float* A  = g_agg;
    const float* X  = (layer == 0) ? xext : (const float*)g_x1;
    float*       Y  = (layer == 0) ? g_x1 : g_x2;
    const float* WT = g_WT + layer * 256 * CDIM;

    int tid  = threadIdx.x;
    int row0 = blockIdx.x * 64;
    int tx = tid & 31, ty = tid >> 5;

    float4 acc[8];
    #pragma unroll
    for (int r = 0; r < 8; r++) acc[r] = make_float4(0.f, 0.f, 0.f, 0.f);

    const float4* WT4 = (const float4*)WT;     // [k][32]
    const float4* A4  = (const float4*)A;      // [row][32]
    const float4* X4  = (const float4*)X;

    for (int c = 0; c < 8; c++) {
        #pragma unroll
        for (int j = 0; j < 4; j++) {
            int idx = tid + j * 256;            // 0..1023
            int kk = idx >> 5, o4 = idx & 31;
            ((float4*)sW)[idx] = WT4[(c * 32 + kk) * 32 + o4];
        }
        #pragma unroll
        for (int j = 0; j < 2; j++) {
            int idx = tid + j * 256;            // 0..511
            int r = idx >> 3, k4 = idx & 7;
            int gr = row0 + r;
            float4 v = make_float4(0.f, 0.f, 0.f, 0.f);
            if (gr < M) {
                const float4* src = (c < 4) ? A4 : X4;
                v = src[(size_t)gr * 32 + (c & 3) * 8 + k4];
            }
            ((float4*)sA)[idx] = v;
        }
        __syncthreads();

        const float4* sWv = (const float4*)sW;  // [kk][32]
        const float4* sAv = (const float4*)sA;  // [row][8]
        #pragma unroll
        for (int kk = 0; kk < 32; kk += 4) {
            float4 b0 = sWv[(kk + 0) * 32 + tx];
            float4 b1 = sWv[(kk + 1) * 32 + tx];
            float4 b2 = sWv[(kk + 2) * 32 + tx];
            float4 b3 = sWv[(kk + 3) * 32 + tx];
            #pragma unroll
            for (int r = 0; r < 8; r++) {
                float4 a = sAv[(ty * 8 + r) * 8 + (kk >> 2)];
                acc[r].x = fmaf(a.w, b3.x, fmaf(a.z, b2.x, fmaf(a.y, b1.x, fmaf(a.x, b0.x, acc[r].x))));
                acc[r].y = fmaf(a.w, b3.y, fmaf(a.z, b2.y, fmaf(a.y, b1.y, fmaf(a.x, b0.y, acc[r].y))));
                acc[r].z = fmaf(a.w, b3.z, fmaf(a.z, b2.z, fmaf(a.y, b1.z, fmaf(a.x, b0.z, acc[r].z))));
                acc[r].w = fmaf(a.w, b3.w, fmaf(a.z, b2.w, fmaf(a.y, b1.w, fmaf(a.x, b0.w, acc[r].w))));
            }
        }
        __syncthreads();
    }

    // epilogue: bias + LayerNorm + ReLU; one warp owns 8 full rows
    float4 bb = make_float4(bias[tx*4], bias[tx*4+1], bias[tx*4+2], bias[tx*4+3]);
    float4 gg = make_float4(gamma[tx*4], gamma[tx*4+1], gamma[tx*4+2], gamma[tx*4+3]);
    float4 be = make_float4(beta[tx*4], beta[tx*4+1], beta[tx*4+2], beta[tx*4+3]);
    float4* Y4 = (float4*)Y;
    #pragma unroll
    for (int r = 0; r < 8; r++) {
        int gr = row0 + ty * 8 + r;
        if (gr >= M) break;   // warp-uniform
        float4 h = acc[r];
        h.x += bb.x; h.y += bb.y; h.z += bb.z; h.w += bb.w;
        float s  = h.x + h.y + h.z + h.w;
        float ss = h.x * h.x + h.y * h.y + h.z * h.z + h.w * h.w;
        #pragma unroll
        for (int o = 16; o; o >>= 1) {
            s  += __shfl_xor_sync(0xffffffffu, s, o);
            ss += __shfl_xor_sync(0xffffffffu, ss, o);
        }
        float mu  = s * (1.f / 128.f);
        float var = ss * (1.f / 128.f) - mu * mu;
        float inv = rsqrtf(var + 1e-5f);
        float4 o4;
        o4.x = fmaxf((h.x - mu) * inv * gg.x + be.x, 0.f);
        o4.y = fmaxf((h.y - mu) * inv * gg.y + be.y, 0.f);
        o4.z = fmaxf((h.z - mu) * inv * gg.z + be.z, 0.f);
        o4.w = fmaxf((h.w - mu) * inv * gg.w + be.w, 0.f);
        Y4[(size_t)gr * 32 + tx] = o4;
    }
}

// ---------------- head: out[NS,64] = g_x2 @ Wh^T + bh ----------------
__global__ void __launch_bounds__(256)
k_head(const float* __restrict__ bh, float* __restrict__ out, int NS)
{
    __shared__ __align__(16) float sW[CDIM * OUTC];   // [k][o]  32KB
    __shared__ __align__(16) float sx[4 * CDIM];
    int tid = threadIdx.x;
    for (int i = tid; i < CDIM * OUTC / 4; i += 256)
        ((float4*)sW)[i] = ((const float4*)g_WhT)[i];
    int row0 = blockIdx.x * 4;
    for (int i = tid; i < 4 * CDIM / 4; i += 256) {
        int r = i >> 5, k4 = i & 31;
        int gr = row0 + r;
        float4 v = make_float4(0.f, 0.f, 0.f, 0.f);
        if (gr < NS) v = ((const float4*)g_x2)[(size_t)gr * 32 + k4];
        ((float4*)sx)[i] = v;
    }
    __syncthreads();
    int r = tid >> 6, o = tid & 63;
    float acc = bh[o];
    #pragma unroll
    for (int k = 0; k < CDIM; k++)
        acc = fmaf(sx[r * CDIM + k], sW[k * OUTC + o], acc);
    int gr = row0 + r;
    if (gr < NS) out[(size_t)gr * OUTC + o] = acc;
}

// ---------------- host launch: kernel launches ONLY ----------------
extern "C" void kernel_launch(void* const* d_in, const int* in_sizes, int n_in,
                              void* d_out, int out_size) {
    const float* x   = (const float*)d_in[0];
    const int*   ei  = (const int*)d_in[1];      // int32! (JAX x64 disabled)
    const float* Wn  = (const float*)d_in[2];
    const float* Wr  = (const float*)d_in[3];
    const float* bc  = (const float*)d_in[4];
    const float* gam = (const float*)d_in[5];
    const float* bet = (const float*)d_in[6];
    const float* Wh  = (const float*)d_in[7];
    const float* bh  = (const float*)d_in[8];

    int N  = in_sizes[0] / CDIM;
    int E  = in_sizes[1] / 2;
    int NS = out_size / OUTC;
    if (N > NMAX) N = NMAX;
    if (E > EMAX) E = EMAX;
    if (NS > SEEDMAX) NS = SEEDMAX;

    const int* srcp = ei;
    const int* dstp = ei + E;

    // CSR build
    k_zero_deg<<<(N + 255) / 256, 256>>>(N);
    k_hist<<<(E + 255) / 256, 256>>>(dstp, E, N);
    k_scan<<<1, 1024>>>(N, E);
    k_fill<<<(E + 255) / 256, 256>>>(srcp, dstp, E, N);
    k_prep<<<(2 * 256 * CDIM + 255) / 256, 256>>>(Wn, Wr, Wh);

    // layer 1 (all N rows)
    k_aggregate<<<(N * 32 + 255) / 256, 256>>>(x, 0, N);
    k_gemm_ln_relu<<<(N + 63) / 64, 256>>>(x, 0, N, bc, gam, bet);

    // layer 2 (only the seed rows feed the head)
    k_aggregate<<<(NS * 32 + 255) / 256, 256>>>(x, 1, NS);
    k_gemm_ln_relu<<<(NS + 63) / 64, 256>>>(x, 1, NS,
                                            bc + CDIM, gam + CDIM, bet + CDIM);

    // head
    k_head<<<(NS + 3) / 4, 256>>>(bh, (float*)d_out, NS);
}

// round 4
// speedup vs baseline: 1.0011x; 1.0011x over previous
#include <cuda_runtime.h>

#define CDIM 128
#define OUTC 64
#define NMAX 50000
#define EMAX 600000
#define SEEDMAX 4096

// packed f32x2 helpers (Blackwell FFMA2 — only reachable via PTX)
#define FMA2(acc, a, b) asm("fma.rn.f32x2 %0, %1, %2, %0;" : "+l"(acc) : "l"(a), "l"(b))
#define PACK2(d, s)     asm("mov.b64 %0, {%1, %1};" : "=l"(d) : "f"(s))
#define UNPACK2(lo, hi, v) asm("mov.b64 {%0, %1}, %2;" : "=f"(lo), "=f"(hi) : "l"(v))

// ---------------- scratch (no allocations allowed; 16B-aligned) ----------------
__device__ __align__(16) int   g_deg[NMAX];
__device__ __align__(16) int   g_off[NMAX + 1];
__device__ __align__(16) int   g_cursor[NMAX];
__device__ __align__(16) int   g_adj[EMAX];
__device__ __align__(16) float g_agg[(size_t)NMAX * CDIM];
__device__ __align__(16) float g_x1[(size_t)NMAX * CDIM];
__device__ __align__(16) float g_x2[(size_t)SEEDMAX * CDIM];
__device__ __align__(16) float g_WT[2 * 256 * CDIM];   // [layer][k 0..255][o 0..127]
__device__ __align__(16) float g_WhT[CDIM * OUTC];     // [k][o]

// ---------------- CSR build ----------------
__global__ void k_zero_deg(int n) {
    int i = blockIdx.x * blockDim.x + threadIdx.x;
    if (i < n) g_deg[i] = 0;
}

// edge_index is int32 on device (JAX x64 disabled downcasts jnp.int64 -> int32)
__global__ void k_hist(const int* __restrict__ dst, int E, int n) {
    int i = blockIdx.x * blockDim.x + threadIdx.x;
    if (i < E) {
        unsigned d = (unsigned)dst[i];
        if (d < (unsigned)n) atomicAdd(&g_deg[d], 1);
    }
}

// single-block exclusive scan over g_deg -> g_off, g_cursor
__global__ void k_scan(int n, int e_total) {
    __shared__ int warp_sums[32];
    __shared__ int s_carry;
    int lane = threadIdx.x & 31, wid = threadIdx.x >> 5;
    if (threadIdx.x == 0) s_carry = 0;
    __syncthreads();
    for (int base = 0; base < n; base += 1024) {
        int i = base + (int)threadIdx.x;
        int v = (i < n) ? g_deg[i] : 0;
        int s = v;
        #pragma unroll
        for (int o = 1; o < 32; o <<= 1) {
            int t = __shfl_up_sync(0xffffffffu, s, o);
            if (lane >= o) s += t;
        }
        if (lane == 31) warp_sums[wid] = s;
        __syncthreads();
        if (wid == 0) {
            int ws = warp_sums[lane];
            int w = ws;
            #pragma unroll
            for (int o = 1; o < 32; o <<= 1) {
                int t = __shfl_up_sync(0xffffffffu, w, o);
                if (lane >= o) w += t;
            }
            warp_sums[lane] = w - ws;   // exclusive prefix of warp sums
        }
        __syncthreads();
        int incl = s + warp_sums[wid] + s_carry;
        int excl = incl - v;
        if (i < n) { g_off[i] = excl; g_cursor[i] = excl; }
        __syncthreads();
        if (threadIdx.x == 1023) s_carry = incl;
        __syncthreads();
    }
    if (threadIdx.x == 0) g_off[n] = e_total;
}

__global__ void k_fill(const int* __restrict__ src,
                       const int* __restrict__ dst, int E, int n) {
    int i = blockIdx.x * blockDim.x + threadIdx.x;
    if (i < E) {
        unsigned d = (unsigned)dst[i];
        unsigned s = (unsigned)src[i];
        if (d < (unsigned)n && s < (unsigned)n) {
            int slot = atomicAdd(&g_cursor[d], 1);
            if (slot < EMAX) g_adj[slot] = (int)s;
        }
    }
}

// ---------------- weight pre-transpose ----------------
__global__ void k_prep(const float* __restrict__ Wn, const float* __restrict__ Wr,
                       const float* __restrict__ Wh) {
    int i = blockIdx.x * blockDim.x + threadIdx.x;
    if (i < 2 * 256 * CDIM) {
        int l = i / (256 * CDIM);
        int rem = i % (256 * CDIM);
        int k = rem / CDIM;
        int o = rem % CDIM;
        float v = (k < CDIM) ? Wn[l * CDIM * CDIM + o * CDIM + k]
                             : Wr[l * CDIM * CDIM + o * CDIM + (k - CDIM)];
        g_WT[i] = v;
    }
    if (i < CDIM * OUTC) {
        int k = i / OUTC, o = i % OUTC;
        g_WhT[i] = Wh[o * CDIM + k];
    }
}

// ---------------- mean aggregation: one warp per node, writes g_agg ----------------
__global__ void k_aggregate(const float* __restrict__ xext, int layer, int M) {
    const float* x = (layer == 0) ? xext : (const float*)g_x1;
    int warp = (int)((blockIdx.x * blockDim.x + threadIdx.x) >> 5);
    int lane = threadIdx.x & 31;
    if (warp >= M) return;
    int s0 = g_off[warp], s1 = g_off[warp + 1];
    float4 acc = make_float4(0.f, 0.f, 0.f, 0.f);
    for (int e = s0; e < s1; e++) {
        int sv = g_adj[e];
        float4 v = __ldg((const float4*)(x + (size_t)sv * CDIM) + lane);
        acc.x += v.x; acc.y += v.y; acc.z += v.z; acc.w += v.w;
    }
    float inv = 1.f / fmaxf((float)(s1 - s0), 1.f);
    float4 out = make_float4(acc.x * inv, acc.y * inv, acc.z * inv, acc.w * inv);
    ((float4*)(g_agg + (size_t)warp * CDIM))[lane] = out;
}

// ---------------- fused GEMM(K=256) + bias + LayerNorm + ReLU ----------------
// h[n][o] = sum_k agg[n][k]*Wn[o][k] + sum_k x[n][k]*Wr[o][k] + b[o]
// 64 rows x 128 cols per block, 256 threads; warp ty owns 8 full rows (LN via
// shuffles). Inner product uses packed fma.rn.f32x2 (FFMA2): acc pairs are 2
// adjacent output columns; weight pairs come free from ulonglong2 smem loads.
__global__ void __launch_bounds__(256)
k_gemm_ln_relu(const float* __restrict__ xext, int layer, int M,
               const float* __restrict__ bias, const float* __restrict__ gamma,
               const float* __restrict__ beta)
{
    __shared__ __align__(16) float sW[32 * CDIM];   // [kk][o]  16KB
    __shared__ __align__(16) float sA[64 * 32];     // [row][kk] 8KB

    const float* A  = g_agg;
    const float* X  = (layer == 0) ? xext : (const float*)g_x1;
    float*       Y  = (layer == 0) ? g_x1 : g_x2;
    const float* WT = g_WT + layer * 256 * CDIM;

    int tid  = threadIdx.x;
    int row0 = blockIdx.x * 64;
    int tx = tid & 31, ty = tid >> 5;

    unsigned long long acc01[8], acc23[8];   // packed {col0,col1}, {col2,col3}
    #pragma unroll
    for (int r = 0; r < 8; r++) { acc01[r] = 0ull; acc23[r] = 0ull; }

    const float4* WT4 = (const float4*)WT;     // [k][32]
    const float4* A4  = (const float4*)A;      // [row][32]
    const float4* X4  = (const float4*)X;

    for (int c = 0; c < 8; c++) {
        #pragma unroll
        for (int j = 0; j < 4; j++) {
            int idx = tid + j * 256;            // 0..1023
            int kk = idx >> 5, o4 = idx & 31;
            ((float4*)sW)[idx] = WT4[(c * 32 + kk) * 32 + o4];
        }
        #pragma unroll
        for (int j = 0; j < 2; j++) {
            int idx = tid + j * 256;            // 0..511
            int r = idx >> 3, k4 = idx & 7;
            int gr = row0 + r;
            float4 v = make_float4(0.f, 0.f, 0.f, 0.f);
            if (gr < M) {
                const float4* src = (c < 4) ? A4 : X4;
                v = src[(size_t)gr * 32 + (c & 3) * 8 + k4];
            }
            ((float4*)sA)[idx] = v;
        }
        __syncthreads();

        const ulonglong2* sWp = (const ulonglong2*)sW;  // [kk][32] pair-of-pairs
        const float4*     sAv = (const float4*)sA;      // [row][8]
        #pragma unroll
        for (int kk = 0; kk < 32; kk += 4) {
            ulonglong2 b0 = sWp[(kk + 0) * 32 + tx];
            ulonglong2 b1 = sWp[(kk + 1) * 32 + tx];
            ulonglong2 b2 = sWp[(kk + 2) * 32 + tx];
            ulonglong2 b3 = sWp[(kk + 3) * 32 + tx];
            #pragma unroll
            for (int r = 0; r < 8; r++) {
                float4 a = sAv[(ty * 8 + r) * 8 + (kk >> 2)];
                unsigned long long aa;
                PACK2(aa, a.x); FMA2(acc01[r], aa, b0.x); FMA2(acc23[r], aa, b0.y);
                PACK2(aa, a.y); FMA2(acc01[r], aa, b1.x); FMA2(acc23[r], aa, b1.y);
                PACK2(aa, a.z); FMA2(acc01[r], aa, b2.x); FMA2(acc23[r], aa, b2.y);
                PACK2(aa, a.w); FMA2(acc01[r], aa, b3.x); FMA2(acc23[r], aa, b3.y);
            }
        }
        __syncthreads();
    }

    // epilogue: bias + LayerNorm + ReLU; one warp owns 8 full rows
    float4 bb = make_float4(bias[tx*4], bias[tx*4+1], bias[tx*4+2], bias[tx*4+3]);
    float4 gg = make_float4(gamma[tx*4], gamma[tx*4+1], gamma[tx*4+2], gamma[tx*4+3]);
    float4 be = make_float4(beta[tx*4], beta[tx*4+1], beta[tx*4+2], beta[tx*4+3]);
    float4* Y4 = (float4*)Y;
    #pragma unroll
    for (int r = 0; r < 8; r++) {
        int gr = row0 + ty * 8 + r;
        if (gr >= M) break;   // warp-uniform
        float4 h;
        UNPACK2(h.x, h.y, acc01[r]);
        UNPACK2(h.z, h.w, acc23[r]);
        h.x += bb.x; h.y += bb.y; h.z += bb.z; h.w += bb.w;
        float s  = h.x + h.y + h.z + h.w;
        float ss = h.x * h.x + h.y * h.y + h.z * h.z + h.w * h.w;
        #pragma unroll
        for (int o = 16; o; o >>= 1) {
            s  += __shfl_xor_sync(0xffffffffu, s, o);
            ss += __shfl_xor_sync(0xffffffffu, ss, o);
        }
        float mu  = s * (1.f / 128.f);
        float var = ss * (1.f / 128.f) - mu * mu;
        float inv = rsqrtf(var + 1e-5f);
        float4 o4;
        o4.x = fmaxf((h.x - mu) * inv * gg.x + be.x, 0.f);
        o4.y = fmaxf((h.y - mu) * inv * gg.y + be.y, 0.f);
        o4.z = fmaxf((h.z - mu) * inv * gg.z + be.z, 0.f);
        o4.w = fmaxf((h.w - mu) * inv * gg.w + be.w, 0.f);
        Y4[(size_t)gr * 32 + tx] = o4;
    }
}

// ---------------- head: out[NS,64] = g_x2 @ Wh^T + bh ----------------
__global__ void __launch_bounds__(256)
k_head(const float* __restrict__ bh, float* __restrict__ out, int NS)
{
    __shared__ __align__(16) float sW[CDIM * OUTC];   // [k][o]  32KB
    __shared__ __align__(16) float sx[4 * CDIM];
    int tid = threadIdx.x;
    for (int i = tid; i < CDIM * OUTC / 4; i += 256)
        ((float4*)sW)[i] = ((const float4*)g_WhT)[i];
    int row0 = blockIdx.x * 4;
    for (int i = tid; i < 4 * CDIM / 4; i += 256) {
        int r = i >> 5, k4 = i & 31;
        int gr = row0 + r;
        float4 v = make_float4(0.f, 0.f, 0.f, 0.f);
        if (gr < NS) v = ((const float4*)g_x2)[(size_t)gr * 32 + k4];
        ((float4*)sx)[i] = v;
    }
    __syncthreads();
    int r = tid >> 6, o = tid & 63;
    float acc = bh[o];
    #pragma unroll
    for (int k = 0; k < CDIM; k++)
        acc = fmaf(sx[r * CDIM + k], sW[k * OUTC + o], acc);
    int gr = row0 + r;
    if (gr < NS) out[(size_t)gr * OUTC + o] = acc;
}

// ---------------- host launch: kernel launches ONLY ----------------
extern "C" void kernel_launch(void* const* d_in, const int* in_sizes, int n_in,
                              void* d_out, int out_size) {
    const float* x   = (const float*)d_in[0];
    const int*   ei  = (const int*)d_in[1];      // int32! (JAX x64 disabled)
    const float* Wn  = (const float*)d_in[2];
    const float* Wr  = (const float*)d_in[3];
    const float* bc  = (const float*)d_in[4];
    const float* gam = (const float*)d_in[5];
    const float* bet = (const float*)d_in[6];
    const float* Wh  = (const float*)d_in[7];
    const float* bh  = (const float*)d_in[8];

    int N  = in_sizes[0] / CDIM;
    int E  = in_sizes[1] / 2;
    int NS = out_size / OUTC;
    if (N > NMAX) N = NMAX;
    if (E > EMAX) E = EMAX;
    if (NS > SEEDMAX) NS = SEEDMAX;

    const int* srcp = ei;
    const int* dstp = ei + E;

    // CSR build
    k_zero_deg<<<(N + 255) / 256, 256>>>(N);
    k_hist<<<(E + 255) / 256, 256>>>(dstp, E, N);
    k_scan<<<1, 1024>>>(N, E);
    k_fill<<<(E + 255) / 256, 256>>>(srcp, dstp, E, N);
    k_prep<<<(2 * 256 * CDIM + 255) / 256, 256>>>(Wn, Wr, Wh);

    // layer 1 (all N rows)
    k_aggregate<<<(N * 32 + 255) / 256, 256>>>(x, 0, N);
    k_gemm_ln_relu<<<(N + 63) / 64, 256>>>(x, 0, N, bc, gam, bet);

    // layer 2 (only the seed rows feed the head)
    k_aggregate<<<(NS * 32 + 255) / 256, 256>>>(x, 1, NS);
    k_gemm_ln_relu<<<(NS + 63) / 64, 256>>>(x, 1, NS,
                                            bc + CDIM, gam + CDIM, bet + CDIM);

    // head
    k_head<<<(NS + 3) / 4, 256>>>(bh, (float*)d_out, NS);
}